// round 3
// baseline (speedup 1.0000x reference)
#include <cuda_runtime.h>
#include <cuda_bf16.h>

typedef unsigned long long ull;

#define BATCH 256
#define NHID  128
#define NBCL  37
#define TSTEPS 12

// activations / state scratch (device globals: no allocation allowed)
__device__ float g_a1[256*30*90*64];
__device__ float g_a2[256*15*45*128];
__device__ float g_a3[256*8*23*128];
__device__ float g_a4[256*4*12*64];
__device__ float g_z0x[TSTEPS*BATCH*4*NHID];   // x-part of layer0 gates, [t*256+b][512]
__device__ float g_h0[2*BATCH*NHID];           // ping-pong h, layer 0
__device__ float g_c0[BATCH*NHID];
__device__ float g_c1[BATCH*NHID];
__device__ float g_hs[TSTEPS*BATCH*NHID];      // layer1 outputs (also its recurrence)
__device__ float g_zero[BATCH*NHID];           // stays zero forever (never written)

__device__ __forceinline__ ull fma2(ull a, ull b, ull c) {
    ull d;
    asm("fma.rn.f32x2 %0, %1, %2, %3;" : "=l"(d) : "l"(a), "l"(b), "l"(c));
    return d;
}
union F2U { ull u; float2 f; };

// ---------------------------------------------------------------------------
// Layer 1: Cin=1 -> Cout=64. One thread = one pooled position x 4 channels.
// ---------------------------------------------------------------------------
__global__ __launch_bounds__(256)
void conv1_kernel(const float* __restrict__ x, const float* __restrict__ wt,
                  const float* __restrict__ cb, const float* __restrict__ gg,
                  const float* __restrict__ bb, const float* __restrict__ mm,
                  const float* __restrict__ mv, float* __restrict__ out)
{
    __shared__ float sw[9*64];
    __shared__ float sbn[128];
    int tid = threadIdx.x;
    if (tid < 64) {
        float s = gg[tid] * rsqrtf(mv[tid] + 1e-5f);
        sbn[tid] = s;
        sbn[64+tid] = (cb[tid]-mm[tid])*s + bb[tid];
    }
    for (int i = tid; i < 576; i += 256) sw[i] = wt[i];
    __syncthreads();

    int idx = blockIdx.x*256 + tid;
    int pw = idx % 90;
    int r1 = idx / 90;
    int ph = r1 % 30;
    int r2 = r1 / 30;
    int b  = r2 & 255;
    int cg = r2 >> 8;   // 0..15

    float xv[4][4];
    const float* xb = x + b*60*180;
    #pragma unroll
    for (int r = 0; r < 4; r++) {
        int hr = 2*ph - 1 + r;
        #pragma unroll
        for (int c = 0; c < 4; c++) {
            int wc = 2*pw - 1 + c;
            float v = 0.f;
            if ((unsigned)hr < 60u && (unsigned)wc < 180u) v = xb[hr*180 + wc];
            xv[r][c] = v;
        }
    }

    const float4* sw4 = (const float4*)sw;
    float4 scale = ((const float4*)sbn)[cg];
    float4 shift = ((const float4*)(sbn+64))[cg];
    float4 best = make_float4(-1e30f,-1e30f,-1e30f,-1e30f);
    #pragma unroll
    for (int dh = 0; dh < 2; dh++) {
        #pragma unroll
        for (int dw = 0; dw < 2; dw++) {
            float4 s = make_float4(0.f,0.f,0.f,0.f);
            #pragma unroll
            for (int i = 0; i < 3; i++) {
                #pragma unroll
                for (int j = 0; j < 3; j++) {
                    float xx = xv[dh+i][dw+j];
                    float4 wv = sw4[(i*3+j)*16 + cg];
                    s.x += xx*wv.x; s.y += xx*wv.y; s.z += xx*wv.z; s.w += xx*wv.w;
                }
            }
            s.x = s.x*scale.x + shift.x; s.y = s.y*scale.y + shift.y;
            s.z = s.z*scale.z + shift.z; s.w = s.w*scale.w + shift.w;
            s.x = s.x < 0.f ? 0.01f*s.x : s.x;
            s.y = s.y < 0.f ? 0.01f*s.y : s.y;
            s.z = s.z < 0.f ? 0.01f*s.z : s.z;
            s.w = s.w < 0.f ? 0.01f*s.w : s.w;
            best.x = fmaxf(best.x, s.x); best.y = fmaxf(best.y, s.y);
            best.z = fmaxf(best.z, s.z); best.w = fmaxf(best.w, s.w);
        }
    }
    ((float4*)out)[((b*30+ph)*90 + pw)*16 + cg] = best;
}

// ---------------------------------------------------------------------------
// Layers 2-4: fused conv+BN+leaky+pool, f32x2 mainloop.
// Tile: 4 rows x 16 cols of conv output, all COUT channels. 256 threads =
// 16 col-threads x 16 channel-group-threads.
// ---------------------------------------------------------------------------
template<int CIN, int COUT>
__global__ __launch_bounds__(256, 2)
void conv_bn_pool(const float* __restrict__ in, const float* __restrict__ wt,
                  const float* __restrict__ cb, const float* __restrict__ gg,
                  const float* __restrict__ bbv, const float* __restrict__ mm,
                  const float* __restrict__ mv,
                  float* __restrict__ out, int H, int W, int PH, int PW)
{
    constexpr int CC   = 16;          // cin chunk
    constexpr int CPT  = COUT/16;     // couts per thread
    constexpr int CP2  = CPT/2;       // f32x2 pairs per thread
    constexpr int LOGC = (COUT == 128) ? 7 : 6;

    extern __shared__ char smem[];
    ull*   xs   = (ull*)smem;                       // [CC][6][18] duplicated x
    float* ws   = (float*)(smem + CC*6*18*8);       // [9][CC][COUT]
    float* obuf = (float*)smem;                     // [64][COUT] (aliased post-loop)
    __shared__ float bnsc[2*COUT];

    int tid = threadIdx.x;
    int tp = tid & 15, tc = tid >> 4;
    if (tid < COUT) {
        float s = gg[tid] * rsqrtf(mv[tid] + 1e-5f);
        bnsc[tid] = s;
        bnsc[COUT+tid] = (cb[tid]-mm[tid])*s + bbv[tid];
    }
    int w0 = blockIdx.x*16, h0 = blockIdx.y*4, b = blockIdx.z;
    const float* inb = in + (size_t)b*H*W*CIN;

    ull acc[4][CP2];
    #pragma unroll
    for (int r = 0; r < 4; r++)
        #pragma unroll
        for (int q = 0; q < CP2; q++) acc[r][q] = 0ull;

    for (int c0 = 0; c0 < CIN; c0 += CC) {
        __syncthreads();
        #pragma unroll 1
        for (int i = tid; i < CC*108; i += 256) {
            int cc = i & 15, p = i >> 4;
            int row = p / 18, col = p - row*18;
            int gh = h0 - 1 + row, gw = w0 - 1 + col;
            float v = 0.f;
            if ((unsigned)gh < (unsigned)H && (unsigned)gw < (unsigned)W)
                v = inb[((size_t)gh*W + gw)*CIN + c0 + cc];
            F2U t; t.f = make_float2(v, v);
            xs[(cc*6+row)*18 + col] = t.u;
        }
        constexpr int SEG4 = CC*COUT/4;
        const float4* w4src = (const float4*)wt;
        float4* w4dst = (float4*)ws;
        #pragma unroll 1
        for (int i = tid; i < 9*SEG4; i += 256) {
            int k9 = i / SEG4, off = i - k9*SEG4;
            w4dst[k9*SEG4 + off] = w4src[(k9*CIN + c0)*(COUT/4) + off];
        }
        __syncthreads();

        #pragma unroll 1
        for (int kh = 0; kh < 3; kh++) {
            #pragma unroll 1
            for (int kw = 0; kw < 3; kw++) {
                const ull*   xp = xs + kh*18 + kw + tp;
                const float* wp = ws + (kh*3+kw)*CC*COUT + tc*CPT;
                #pragma unroll
                for (int cc = 0; cc < CC; cc++) {
                    ull x0 = xp[cc*108];
                    ull x1 = xp[cc*108 + 18];
                    ull x2 = xp[cc*108 + 36];
                    ull x3 = xp[cc*108 + 54];
                    #pragma unroll
                    for (int q2 = 0; q2 < CP2; q2 += 2) {
                        union { float4 f4; ull u[2]; } Wv;
                        Wv.f4 = *(const float4*)(wp + cc*COUT + 2*q2);
                        acc[0][q2]   = fma2(x0, Wv.u[0], acc[0][q2]);
                        acc[1][q2]   = fma2(x1, Wv.u[0], acc[1][q2]);
                        acc[2][q2]   = fma2(x2, Wv.u[0], acc[2][q2]);
                        acc[3][q2]   = fma2(x3, Wv.u[0], acc[3][q2]);
                        acc[0][q2+1] = fma2(x0, Wv.u[1], acc[0][q2+1]);
                        acc[1][q2+1] = fma2(x1, Wv.u[1], acc[1][q2+1]);
                        acc[2][q2+1] = fma2(x2, Wv.u[1], acc[2][q2+1]);
                        acc[3][q2+1] = fma2(x3, Wv.u[1], acc[3][q2+1]);
                    }
                }
            }
        }
    }
    __syncthreads();
    #pragma unroll
    for (int r = 0; r < 4; r++) {
        #pragma unroll
        for (int q = 0; q < CP2; q++) {
            F2U v; v.u = acc[r][q];
            int cidx = tc*CPT + 2*q;
            float y0 = v.f.x*bnsc[cidx]   + bnsc[COUT+cidx];
            float y1 = v.f.y*bnsc[cidx+1] + bnsc[COUT+cidx+1];
            y0 = y0 < 0.f ? 0.01f*y0 : y0;
            y1 = y1 < 0.f ? 0.01f*y1 : y1;
            *(float2*)&obuf[(r*16+tp)*COUT + cidx] = make_float2(y0, y1);
        }
    }
    __syncthreads();
    #pragma unroll 1
    for (int i = tid; i < 16*COUT; i += 256) {
        int cout = i & (COUT-1);
        int pp = i >> LOGC;
        int pr = pp >> 3, pc = pp & 7;
        float m = -1e30f;
        #pragma unroll
        for (int dr = 0; dr < 2; dr++) {
            #pragma unroll
            for (int dc = 0; dc < 2; dc++) {
                int lr = 2*pr+dr, lc = 2*pc+dc;
                if (h0+lr < H && w0+lc < W)
                    m = fmaxf(m, obuf[(lr*16+lc)*COUT + cout]);
            }
        }
        int gph = (h0>>1) + pr, gpw = (w0>>1) + pc;
        if (gph < PH && gpw < PW)
            out[((size_t)(b*PH+gph)*PW + gpw)*COUT + cout] = m;
    }
}

// ---------------------------------------------------------------------------
// z0x[t*256+b][n] = x_seq[t,b,:] @ lW0[0:256,n] + lb0[n];  M=3072,N=512,K=256
// x_seq[t,b,d] = a4[b, d>>6, t, d&63]
// ---------------------------------------------------------------------------
__global__ __launch_bounds__(256)
void z0x_kernel(const float* __restrict__ lW0, const float* __restrict__ lb0)
{
    __shared__ float As[64][17];
    __shared__ float Bs[16][64];
    int tid = threadIdx.x;
    int tx = tid & 15, ty = tid >> 4;
    int m0 = blockIdx.y*64, n0 = blockIdx.x*64;
    float acc[4][4] = {};
    for (int k0 = 0; k0 < 256; k0 += 16) {
        __syncthreads();
        #pragma unroll 1
        for (int i = tid; i < 1024; i += 256) {
            int mr = i >> 4, kk = i & 15;
            int m = m0 + mr; int t = m >> 8; int b = m & 255;
            int d = k0 + kk; int h = d >> 6; int c = d & 63;
            As[mr][kk] = g_a4[(((b<<2)+h)*12 + t)*64 + c];
            int kk2 = i >> 6, col = i & 63;
            Bs[kk2][col] = lW0[(k0+kk2)*512 + n0 + col];
        }
        __syncthreads();
        #pragma unroll
        for (int kk = 0; kk < 16; kk++) {
            float a[4], bv[4];
            #pragma unroll
            for (int r = 0; r < 4; r++) a[r] = As[ty+16*r][kk];
            #pragma unroll
            for (int c = 0; c < 4; c++) bv[c] = Bs[kk][tx+16*c];
            #pragma unroll
            for (int r = 0; r < 4; r++)
                #pragma unroll
                for (int c = 0; c < 4; c++) acc[r][c] += a[r]*bv[c];
        }
    }
    #pragma unroll
    for (int r = 0; r < 4; r++)
        #pragma unroll
        for (int c = 0; c < 4; c++) {
            int m = m0 + ty + 16*r, n = n0 + tx + 16*c;
            g_z0x[m*512 + n] = acc[r][c] + lb0[n];
        }
}

// ---------------------------------------------------------------------------
// One LSTM layer step. z = [A0|A1] @ Wmat (+ zb[m][...] or bias), TF gating.
// grid (4,16), 128 threads: 32 n-cols x 4 gates x 16 batch rows per block.
// ---------------------------------------------------------------------------
__device__ __forceinline__ float sigm(float x) { return 1.f/(1.f + __expf(-x)); }

__global__ __launch_bounds__(128)
void lstm_step(const float* __restrict__ A0, const float* __restrict__ A1,
               int K0, int K1,
               const float* __restrict__ Wmat,
               const float* __restrict__ zb,    // [256][512] or null
               const float* __restrict__ bias,  // [512] or null
               float* __restrict__ c_io, float* __restrict__ h_out)
{
    __shared__ float As[16][17];
    __shared__ float Ws[16][128];
    int tid = threadIdx.x;
    int tn = tid & 31, tq = tid >> 5;
    int n0 = blockIdx.x*32, m0 = blockIdx.y*16;
    int Ktot = K0 + K1;
    float acc[4][4] = {};   // [row][gate]
    for (int k0 = 0; k0 < Ktot; k0 += 16) {
        __syncthreads();
        #pragma unroll 1
        for (int i = tid; i < 256; i += 128) {
            int r = i >> 4, kk = i & 15;
            int kg = k0 + kk;
            As[r][kk] = (kg < K0) ? A0[(m0+r)*K0 + kg] : A1[(m0+r)*K1 + (kg-K0)];
        }
        #pragma unroll 1
        for (int i = tid; i < 2048; i += 128) {
            int kk = i >> 7, col = i & 127;
            int gate = col >> 5, nn = col & 31;
            Ws[kk][col] = Wmat[(size_t)(k0+kk)*512 + gate*128 + n0 + nn];
        }
        __syncthreads();
        #pragma unroll
        for (int kk = 0; kk < 16; kk++) {
            float a[4], w[4];
            #pragma unroll
            for (int r = 0; r < 4; r++) a[r] = As[tq + 4*r][kk];
            #pragma unroll
            for (int g = 0; g < 4; g++) w[g] = Ws[kk][g*32 + tn];
            #pragma unroll
            for (int r = 0; r < 4; r++)
                #pragma unroll
                for (int g = 0; g < 4; g++) acc[r][g] += a[r]*w[g];
        }
    }
    int n = n0 + tn;
    #pragma unroll
    for (int r = 0; r < 4; r++) {
        int m = m0 + tq + 4*r;
        float zi, zj, zf, zo;
        if (zb) {
            zi = acc[r][0] + zb[m*512 + 0*128 + n];
            zj = acc[r][1] + zb[m*512 + 1*128 + n];
            zf = acc[r][2] + zb[m*512 + 2*128 + n];
            zo = acc[r][3] + zb[m*512 + 3*128 + n];
        } else {
            zi = acc[r][0] + bias[0*128 + n];
            zj = acc[r][1] + bias[1*128 + n];
            zf = acc[r][2] + bias[2*128 + n];
            zo = acc[r][3] + bias[3*128 + n];
        }
        float c = c_io[m*128 + n];
        float cn = c*sigm(zf + 1.0f) + sigm(zi)*tanhf(zj);
        c_io[m*128 + n] = cn;
        h_out[m*128 + n] = tanhf(cn)*sigm(zo);
    }
}

// ---------------------------------------------------------------------------
// logits = hs @ Wout + bout  -> [12,256,37] time-major (matches reference)
// ---------------------------------------------------------------------------
__global__ __launch_bounds__(256)
void logits_kernel(const float* __restrict__ Wout, const float* __restrict__ bout,
                   float* __restrict__ out)
{
    __shared__ float sW[128*37];
    __shared__ float sb[37];
    int tid = threadIdx.x;
    for (int i = tid; i < 128*37; i += 256) sW[i] = Wout[i];
    if (tid < 37) sb[tid] = bout[tid];
    __syncthreads();
    int idx = blockIdx.x*256 + tid;   // exactly 12*256*37 = 113664
    int nb = idx % 37;
    int m  = idx / 37;
    const float* h = g_hs + m*128;
    float s = 0.f;
    #pragma unroll 8
    for (int k = 0; k < 128; k++) s += h[k]*sW[k*37 + nb];
    out[idx] = s + sb[nb];
}

// ---------------------------------------------------------------------------
// host
// ---------------------------------------------------------------------------
extern "C" void kernel_launch(void* const* d_in, const int* in_sizes, int n_in,
                              void* d_out, int out_size)
{
    const float* x = (const float*)d_in[0];
    const float *cw[4], *ccb[4], *cgm[4], *cbb[4], *cmm[4], *cmv[4];
    for (int i = 0; i < 4; i++) {
        cw[i]  = (const float*)d_in[1 + 6*i + 0];
        ccb[i] = (const float*)d_in[1 + 6*i + 1];
        cgm[i] = (const float*)d_in[1 + 6*i + 2];
        cbb[i] = (const float*)d_in[1 + 6*i + 3];
        cmm[i] = (const float*)d_in[1 + 6*i + 4];
        cmv[i] = (const float*)d_in[1 + 6*i + 5];
    }
    const float* lW0  = (const float*)d_in[25];
    const float* lb0  = (const float*)d_in[26];
    const float* lW1  = (const float*)d_in[27];
    const float* lb1  = (const float*)d_in[28];
    const float* Wout = (const float*)d_in[29];
    const float* bout = (const float*)d_in[30];
    float* out = (float*)d_out;

    float *a1, *a2, *a3, *a4, *z0x, *h0, *c0, *c1, *hs, *zro;
    cudaGetSymbolAddress((void**)&a1,  g_a1);
    cudaGetSymbolAddress((void**)&a2,  g_a2);
    cudaGetSymbolAddress((void**)&a3,  g_a3);
    cudaGetSymbolAddress((void**)&a4,  g_a4);
    cudaGetSymbolAddress((void**)&z0x, g_z0x);
    cudaGetSymbolAddress((void**)&h0,  g_h0);
    cudaGetSymbolAddress((void**)&c0,  g_c0);
    cudaGetSymbolAddress((void**)&c1,  g_c1);
    cudaGetSymbolAddress((void**)&hs,  g_hs);
    cudaGetSymbolAddress((void**)&zro, g_zero);

    cudaFuncSetAttribute(conv_bn_pool<64,128>,  cudaFuncAttributeMaxDynamicSharedMemorySize, 87552);
    cudaFuncSetAttribute(conv_bn_pool<128,128>, cudaFuncAttributeMaxDynamicSharedMemorySize, 87552);
    cudaFuncSetAttribute(conv_bn_pool<128,64>,  cudaFuncAttributeMaxDynamicSharedMemorySize, 50688);

    // ---- conv stack ----
    conv1_kernel<<<43200, 256>>>(x, cw[0], ccb[0], cgm[0], cbb[0], cmm[0], cmv[0], a1);

    dim3 g2((90+15)/16, (30+3)/4, 256);   // 6 x 8 x 256
    conv_bn_pool<64,128><<<g2, 256, 87552>>>(a1, cw[1], ccb[1], cgm[1], cbb[1],
                                             cmm[1], cmv[1], a2, 30, 90, 15, 45);
    dim3 g3((45+15)/16, (15+3)/4, 256);   // 3 x 4 x 256
    conv_bn_pool<128,128><<<g3, 256, 87552>>>(a2, cw[2], ccb[2], cgm[2], cbb[2],
                                              cmm[2], cmv[2], a3, 15, 45, 8, 23);
    dim3 g4((23+15)/16, (8+3)/4, 256);    // 2 x 2 x 256
    conv_bn_pool<128,64><<<g4, 256, 50688>>>(a3, cw[3], ccb[3], cgm[3], cbb[3],
                                             cmm[3], cmv[3], a4, 8, 23, 4, 12);

    // ---- LSTM ----
    z0x_kernel<<<dim3(8, 48), 256>>>(lW0, lb0);
    cudaMemsetAsync(c0, 0, BATCH*NHID*sizeof(float));
    cudaMemsetAsync(c1, 0, BATCH*NHID*sizeof(float));

    for (int t = 0; t < TSTEPS; t++) {
        const float* h0_prev = (t == 0) ? zro : h0 + ((t+1)&1)*BATCH*NHID;
        float*       h0_out  = h0 + (t&1)*BATCH*NHID;
        // layer 0: gates = z0x[t] + h0_prev @ lW0[256:384,:]
        lstm_step<<<dim3(4,16), 128>>>(h0_prev, zro, NHID, 0,
                                       lW0 + 256*512,
                                       z0x + (size_t)t*BATCH*512, nullptr,
                                       c0, h0_out);
        // layer 1: gates = [h0_out | h1_prev] @ lW1 + lb1
        const float* h1_prev = (t == 0) ? zro : hs + (size_t)(t-1)*BATCH*NHID;
        lstm_step<<<dim3(4,16), 128>>>(h0_out, h1_prev, NHID, NHID,
                                       lW1, nullptr, lb1,
                                       c1, hs + (size_t)t*BATCH*NHID);
    }

    // ---- projection ----
    logits_kernel<<<444, 256>>>(Wout, bout, out);
}

// round 7
// speedup vs baseline: 1.1446x; 1.1446x over previous
#include <cuda_runtime.h>
#include <cuda_bf16.h>

typedef unsigned long long ull;

#define BATCH 256
#define NHID  128
#define NBCL  37
#define TSTEPS 12

// activations / state scratch (device globals: no allocation allowed)
__device__ float g_a1[256*30*90*64];
__device__ float g_a2[256*15*45*128];
__device__ float g_a3[256*8*23*128];
__device__ float g_a4[256*4*12*64];
__device__ float g_z0x[TSTEPS*BATCH*4*NHID];   // x-part of layer0 gates, [t*256+b][512]
__device__ float g_h0[2*BATCH*NHID];           // ping-pong h, layer 0
__device__ float g_c0[BATCH*NHID];
__device__ float g_c1[BATCH*NHID];
__device__ float g_hs[TSTEPS*BATCH*NHID];      // layer1 outputs (also its recurrence)
__device__ float g_zero[BATCH*NHID];           // stays zero forever (never written)

__device__ __forceinline__ ull fma2(ull a, ull b, ull c) {
    ull d;
    asm("fma.rn.f32x2 %0, %1, %2, %3;" : "=l"(d) : "l"(a), "l"(b), "l"(c));
    return d;
}
union F2U { ull u; float2 f; };

// ---------------------------------------------------------------------------
// Layer 1: Cin=1 -> Cout=64. One thread = one pooled position x 4 channels.
// ---------------------------------------------------------------------------
__global__ __launch_bounds__(256)
void conv1_kernel(const float* __restrict__ x, const float* __restrict__ wt,
                  const float* __restrict__ cb, const float* __restrict__ gg,
                  const float* __restrict__ bb, const float* __restrict__ mm,
                  const float* __restrict__ mv, float* __restrict__ out)
{
    __shared__ float sw[9*64];
    __shared__ float sbn[128];
    int tid = threadIdx.x;
    if (tid < 64) {
        float s = gg[tid] * rsqrtf(mv[tid] + 1e-5f);
        sbn[tid] = s;
        sbn[64+tid] = (cb[tid]-mm[tid])*s + bb[tid];
    }
    for (int i = tid; i < 576; i += 256) sw[i] = wt[i];
    __syncthreads();

    int idx = blockIdx.x*256 + tid;
    int pw = idx % 90;
    int r1 = idx / 90;
    int ph = r1 % 30;
    int r2 = r1 / 30;
    int b  = r2 & 255;
    int cg = r2 >> 8;   // 0..15

    float xv[4][4];
    const float* xb = x + b*60*180;
    #pragma unroll
    for (int r = 0; r < 4; r++) {
        int hr = 2*ph - 1 + r;
        #pragma unroll
        for (int c = 0; c < 4; c++) {
            int wc = 2*pw - 1 + c;
            float v = 0.f;
            if ((unsigned)hr < 60u && (unsigned)wc < 180u) v = xb[hr*180 + wc];
            xv[r][c] = v;
        }
    }

    const float4* sw4 = (const float4*)sw;
    float4 scale = ((const float4*)sbn)[cg];
    float4 shift = ((const float4*)(sbn+64))[cg];
    float4 best = make_float4(-1e30f,-1e30f,-1e30f,-1e30f);
    #pragma unroll
    for (int dh = 0; dh < 2; dh++) {
        #pragma unroll
        for (int dw = 0; dw < 2; dw++) {
            float4 s = make_float4(0.f,0.f,0.f,0.f);
            #pragma unroll
            for (int i = 0; i < 3; i++) {
                #pragma unroll
                for (int j = 0; j < 3; j++) {
                    float xx = xv[dh+i][dw+j];
                    float4 wv = sw4[(i*3+j)*16 + cg];
                    s.x += xx*wv.x; s.y += xx*wv.y; s.z += xx*wv.z; s.w += xx*wv.w;
                }
            }
            s.x = s.x*scale.x + shift.x; s.y = s.y*scale.y + shift.y;
            s.z = s.z*scale.z + shift.z; s.w = s.w*scale.w + shift.w;
            s.x = s.x < 0.f ? 0.01f*s.x : s.x;
            s.y = s.y < 0.f ? 0.01f*s.y : s.y;
            s.z = s.z < 0.f ? 0.01f*s.z : s.z;
            s.w = s.w < 0.f ? 0.01f*s.w : s.w;
            best.x = fmaxf(best.x, s.x); best.y = fmaxf(best.y, s.y);
            best.z = fmaxf(best.z, s.z); best.w = fmaxf(best.w, s.w);
        }
    }
    ((float4*)out)[((b*30+ph)*90 + pw)*16 + cg] = best;
}

// ---------------------------------------------------------------------------
// Layers 2-4: fused conv+BN+leaky+pool, f32x2 mainloop with kh-reuse.
// Tile: 6 rows x 16 cols of conv output, all COUT channels.
// 256 threads = 16 col-threads x 16 channel-group-threads.
// Per cin, an 8-row x-window is staged; each x-pair load feeds up to 3 kh
// positions; w for all 3 kh live in registers -> ~40 crossbar-cyc per
// 72 fma2 (near fma-bound) vs 3:1 crossbar-bound before.
// ---------------------------------------------------------------------------
template<int CIN, int COUT>
__global__ __launch_bounds__(256, 2)
void conv_bn_pool(const float* __restrict__ in, const float* __restrict__ wt,
                  const float* __restrict__ cb, const float* __restrict__ gg,
                  const float* __restrict__ bbv, const float* __restrict__ mm,
                  const float* __restrict__ mv,
                  float* __restrict__ out, int H, int W, int PH, int PW)
{
    constexpr int CC   = 16;          // cin chunk
    constexpr int CPT  = COUT/16;     // couts per thread (8 or 4)
    constexpr int CP2  = CPT/2;       // f32x2 pairs per thread (4 or 2)
    constexpr int NW4  = CP2/2 > 0 ? CP2/2 : 1;  // float4 weight vectors (2 or 1)
    constexpr int LOGC = (COUT == 128) ? 7 : 6;
    constexpr int XS_ULL = CC*8*18;   // 2304 x-pairs

    extern __shared__ char smem[];
    ull*   xs   = (ull*)smem;                     // [CC][8][18] duplicated x
    float* ws   = (float*)(smem + XS_ULL*8);      // [9][CC][COUT]
    float* obuf = (float*)smem;                   // [96][COUT] (aliased post-loop)
    __shared__ float bnsc[2*COUT];

    int tid = threadIdx.x;
    int tp = tid & 15, tc = tid >> 4;
    if (tid < COUT) {
        float s = gg[tid] * rsqrtf(mv[tid] + 1e-5f);
        bnsc[tid] = s;
        bnsc[COUT+tid] = (cb[tid]-mm[tid])*s + bbv[tid];
    }
    int w0 = blockIdx.x*16, h0 = blockIdx.y*6, b = blockIdx.z;
    const float* inb = in + (size_t)b*H*W*CIN;

    ull acc[6][CP2];
    #pragma unroll
    for (int r = 0; r < 6; r++)
        #pragma unroll
        for (int q = 0; q < CP2; q++) acc[r][q] = 0ull;

    for (int c0 = 0; c0 < CIN; c0 += CC) {
        __syncthreads();
        // stage x window: rows h0-1 .. h0+6, cols w0-1 .. w0+16, duplicated pairs
        #pragma unroll 1
        for (int i = tid; i < CC*144; i += 256) {
            int cc = i & 15, p = i >> 4;
            int row = p / 18, col = p - row*18;
            int gh = h0 - 1 + row, gw = w0 - 1 + col;
            float v = 0.f;
            if ((unsigned)gh < (unsigned)H && (unsigned)gw < (unsigned)W)
                v = inb[((size_t)gh*W + gw)*CIN + c0 + cc];
            F2U t; t.f = make_float2(v, v);
            xs[(cc*8+row)*18 + col] = t.u;
        }
        // stage weights [9][CC][COUT]
        constexpr int SEG4 = CC*COUT/4;
        const float4* w4src = (const float4*)wt;
        float4* w4dst = (float4*)ws;
        #pragma unroll 1
        for (int i = tid; i < 9*SEG4; i += 256) {
            int k9 = i / SEG4, off = i - k9*SEG4;
            w4dst[k9*SEG4 + off] = w4src[(k9*CIN + c0)*(COUT/4) + off];
        }
        __syncthreads();

        #pragma unroll 1
        for (int cc = 0; cc < 16; cc++) {
            const ull* xb = xs + (cc*8)*18 + tp;
            #pragma unroll
            for (int kw = 0; kw < 3; kw++) {
                // weights for all 3 kh in registers
                union { float4 f4; ull u[2]; } wv[3][NW4];
                #pragma unroll
                for (int kh = 0; kh < 3; kh++)
                    #pragma unroll
                    for (int j = 0; j < NW4; j++)
                        wv[kh][j].f4 = *(const float4*)(ws +
                            ((kh*3+kw)*CC + cc)*COUT + tc*CPT + 4*j);

                #pragma unroll
                for (int wr = 0; wr < 8; wr++) {
                    ull x = xb[wr*18 + kw];
                    #pragma unroll
                    for (int kh = 0; kh < 3; kh++) {
                        if (wr - kh >= 0 && wr - kh < 6) {
                            int r = wr - kh;
                            #pragma unroll
                            for (int j = 0; j < NW4; j++) {
                                acc[r][2*j]   = fma2(x, wv[kh][j].u[0], acc[r][2*j]);
                                if (CP2 > 1)
                                    acc[r][2*j+1] = fma2(x, wv[kh][j].u[1], acc[r][2*j+1]);
                            }
                        }
                    }
                }
            }
        }
    }
    __syncthreads();
    // BN + leaky -> obuf [96][COUT]
    #pragma unroll
    for (int r = 0; r < 6; r++) {
        #pragma unroll
        for (int q = 0; q < CP2; q++) {
            F2U v; v.u = acc[r][q];
            int cidx = tc*CPT + 2*q;
            float y0 = v.f.x*bnsc[cidx]   + bnsc[COUT+cidx];
            float y1 = v.f.y*bnsc[cidx+1] + bnsc[COUT+cidx+1];
            y0 = y0 < 0.f ? 0.01f*y0 : y0;
            y1 = y1 < 0.f ? 0.01f*y1 : y1;
            *(float2*)&obuf[(r*16+tp)*COUT + cidx] = make_float2(y0, y1);
        }
    }
    __syncthreads();
    // 2x2 SAME maxpool: pooled tile 3 rows x 8 cols
    #pragma unroll 1
    for (int i = tid; i < 24*COUT; i += 256) {
        int cout = i & (COUT-1);
        int pp = i >> LOGC;           // 0..23
        int pr = pp >> 3, pc = pp & 7;
        float m = -1e30f;
        #pragma unroll
        for (int dr = 0; dr < 2; dr++) {
            #pragma unroll
            for (int dc = 0; dc < 2; dc++) {
                int lr = 2*pr+dr, lc = 2*pc+dc;
                if (h0+lr < H && w0+lc < W)
                    m = fmaxf(m, obuf[(lr*16+lc)*COUT + cout]);
            }
        }
        int gph = (h0>>1) + pr, gpw = (w0>>1) + pc;
        if (gph < PH && gpw < PW)
            out[((size_t)(b*PH+gph)*PW + gpw)*COUT + cout] = m;
    }
}

// ---------------------------------------------------------------------------
// z0x[t*256+b][n] = x_seq[t,b,:] @ lW0[0:256,n] + lb0[n];  M=3072,N=512,K=256
// x_seq[t,b,d] = a4[b, d>>6, t, d&63]
// ---------------------------------------------------------------------------
__global__ __launch_bounds__(256)
void z0x_kernel(const float* __restrict__ lW0, const float* __restrict__ lb0)
{
    __shared__ float As[64][17];
    __shared__ float Bs[16][64];
    int tid = threadIdx.x;
    int tx = tid & 15, ty = tid >> 4;
    int m0 = blockIdx.y*64, n0 = blockIdx.x*64;
    float acc[4][4] = {};
    for (int k0 = 0; k0 < 256; k0 += 16) {
        __syncthreads();
        #pragma unroll 1
        for (int i = tid; i < 1024; i += 256) {
            int mr = i >> 4, kk = i & 15;
            int m = m0 + mr; int t = m >> 8; int b = m & 255;
            int d = k0 + kk; int h = d >> 6; int c = d & 63;
            As[mr][kk] = g_a4[(((b<<2)+h)*12 + t)*64 + c];
            int kk2 = i >> 6, col = i & 63;
            Bs[kk2][col] = lW0[(k0+kk2)*512 + n0 + col];
        }
        __syncthreads();
        #pragma unroll
        for (int kk = 0; kk < 16; kk++) {
            float a[4], bv[4];
            #pragma unroll
            for (int r = 0; r < 4; r++) a[r] = As[ty+16*r][kk];
            #pragma unroll
            for (int c = 0; c < 4; c++) bv[c] = Bs[kk][tx+16*c];
            #pragma unroll
            for (int r = 0; r < 4; r++)
                #pragma unroll
                for (int c = 0; c < 4; c++) acc[r][c] += a[r]*bv[c];
        }
    }
    #pragma unroll
    for (int r = 0; r < 4; r++)
        #pragma unroll
        for (int c = 0; c < 4; c++) {
            int m = m0 + ty + 16*r, n = n0 + tx + 16*c;
            g_z0x[m*512 + n] = acc[r][c] + lb0[n];
        }
}

// ---------------------------------------------------------------------------
// One LSTM layer step. z = [A0|A1] @ Wmat (+ zb[m][...] or bias), TF gating.
// grid (4,16), 128 threads: 32 n-cols x 4 gates x 16 batch rows per block.
// ---------------------------------------------------------------------------
__device__ __forceinline__ float sigm(float x) { return 1.f/(1.f + __expf(-x)); }

__global__ __launch_bounds__(128)
void lstm_step(const float* __restrict__ A0, const float* __restrict__ A1,
               int K0, int K1,
               const float* __restrict__ Wmat,
               const float* __restrict__ zb,    // [256][512] or null
               const float* __restrict__ bias,  // [512] or null
               float* __restrict__ c_io, float* __restrict__ h_out)
{
    __shared__ float As[16][17];
    __shared__ float Ws[16][128];
    int tid = threadIdx.x;
    int tn = tid & 31, tq = tid >> 5;
    int n0 = blockIdx.x*32, m0 = blockIdx.y*16;
    int Ktot = K0 + K1;
    float acc[4][4] = {};   // [row][gate]
    for (int k0 = 0; k0 < Ktot; k0 += 16) {
        __syncthreads();
        #pragma unroll 1
        for (int i = tid; i < 256; i += 128) {
            int r = i >> 4, kk = i & 15;
            int kg = k0 + kk;
            As[r][kk] = (kg < K0) ? A0[(m0+r)*K0 + kg] : A1[(m0+r)*K1 + (kg-K0)];
        }
        #pragma unroll 1
        for (int i = tid; i < 2048; i += 128) {
            int kk = i >> 7, col = i & 127;
            int gate = col >> 5, nn = col & 31;
            Ws[kk][col] = Wmat[(size_t)(k0+kk)*512 + gate*128 + n0 + nn];
        }
        __syncthreads();
        #pragma unroll
        for (int kk = 0; kk < 16; kk++) {
            float a[4], w[4];
            #pragma unroll
            for (int r = 0; r < 4; r++) a[r] = As[tq + 4*r][kk];
            #pragma unroll
            for (int g = 0; g < 4; g++) w[g] = Ws[kk][g*32 + tn];
            #pragma unroll
            for (int r = 0; r < 4; r++)
                #pragma unroll
                for (int g = 0; g < 4; g++) acc[r][g] += a[r]*w[g];
        }
    }
    int n = n0 + tn;
    #pragma unroll
    for (int r = 0; r < 4; r++) {
        int m = m0 + tq + 4*r;
        float zi, zj, zf, zo;
        if (zb) {
            zi = acc[r][0] + zb[m*512 + 0*128 + n];
            zj = acc[r][1] + zb[m*512 + 1*128 + n];
            zf = acc[r][2] + zb[m*512 + 2*128 + n];
            zo = acc[r][3] + zb[m*512 + 3*128 + n];
        } else {
            zi = acc[r][0] + bias[0*128 + n];
            zj = acc[r][1] + bias[1*128 + n];
            zf = acc[r][2] + bias[2*128 + n];
            zo = acc[r][3] + bias[3*128 + n];
        }
        float c = c_io[m*128 + n];
        float cn = c*sigm(zf + 1.0f) + sigm(zi)*tanhf(zj);
        c_io[m*128 + n] = cn;
        h_out[m*128 + n] = tanhf(cn)*sigm(zo);
    }
}

// ---------------------------------------------------------------------------
// logits = hs @ Wout + bout  -> [12,256,37] time-major (matches reference)
// ---------------------------------------------------------------------------
__global__ __launch_bounds__(256)
void logits_kernel(const float* __restrict__ Wout, const float* __restrict__ bout,
                   float* __restrict__ out)
{
    __shared__ float sW[128*37];
    __shared__ float sb[37];
    int tid = threadIdx.x;
    for (int i = tid; i < 128*37; i += 256) sW[i] = Wout[i];
    if (tid < 37) sb[tid] = bout[tid];
    __syncthreads();
    int idx = blockIdx.x*256 + tid;   // exactly 12*256*37 = 113664
    int nb = idx % 37;
    int m  = idx / 37;
    const float* h = g_hs + m*128;
    float s = 0.f;
    #pragma unroll 8
    for (int k = 0; k < 128; k++) s += h[k]*sW[k*37 + nb];
    out[idx] = s + sb[nb];
}

// ---------------------------------------------------------------------------
// host
// ---------------------------------------------------------------------------
extern "C" void kernel_launch(void* const* d_in, const int* in_sizes, int n_in,
                              void* d_out, int out_size)
{
    const float* x = (const float*)d_in[0];
    const float *cw[4], *ccb[4], *cgm[4], *cbb[4], *cmm[4], *cmv[4];
    for (int i = 0; i < 4; i++) {
        cw[i]  = (const float*)d_in[1 + 6*i + 0];
        ccb[i] = (const float*)d_in[1 + 6*i + 1];
        cgm[i] = (const float*)d_in[1 + 6*i + 2];
        cbb[i] = (const float*)d_in[1 + 6*i + 3];
        cmm[i] = (const float*)d_in[1 + 6*i + 4];
        cmv[i] = (const float*)d_in[1 + 6*i + 5];
    }
    const float* lW0  = (const float*)d_in[25];
    const float* lb0  = (const float*)d_in[26];
    const float* lW1  = (const float*)d_in[27];
    const float* lb1  = (const float*)d_in[28];
    const float* Wout = (const float*)d_in[29];
    const float* bout = (const float*)d_in[30];
    float* out = (float*)d_out;

    float *a1, *a2, *a3, *a4, *z0x, *h0, *c0, *c1, *hs, *zro;
    cudaGetSymbolAddress((void**)&a1,  g_a1);
    cudaGetSymbolAddress((void**)&a2,  g_a2);
    cudaGetSymbolAddress((void**)&a3,  g_a3);
    cudaGetSymbolAddress((void**)&a4,  g_a4);
    cudaGetSymbolAddress((void**)&z0x, g_z0x);
    cudaGetSymbolAddress((void**)&h0,  g_h0);
    cudaGetSymbolAddress((void**)&c0,  g_c0);
    cudaGetSymbolAddress((void**)&c1,  g_c1);
    cudaGetSymbolAddress((void**)&hs,  g_hs);
    cudaGetSymbolAddress((void**)&zro, g_zero);

    // smem: xs 2304*8 = 18432 B; ws 9*16*COUT*4 B
    cudaFuncSetAttribute(conv_bn_pool<64,128>,  cudaFuncAttributeMaxDynamicSharedMemorySize, 92160);
    cudaFuncSetAttribute(conv_bn_pool<128,128>, cudaFuncAttributeMaxDynamicSharedMemorySize, 92160);
    cudaFuncSetAttribute(conv_bn_pool<128,64>,  cudaFuncAttributeMaxDynamicSharedMemorySize, 55296);

    // ---- conv stack ----
    conv1_kernel<<<43200, 256>>>(x, cw[0], ccb[0], cgm[0], cbb[0], cmm[0], cmv[0], a1);

    dim3 g2(6, 5, 256);   // 90/16, 30/6
    conv_bn_pool<64,128><<<g2, 256, 92160>>>(a1, cw[1], ccb[1], cgm[1], cbb[1],
                                             cmm[1], cmv[1], a2, 30, 90, 15, 45);
    dim3 g3(3, 3, 256);   // 45/16, 15/6
    conv_bn_pool<128,128><<<g3, 256, 92160>>>(a2, cw[2], ccb[2], cgm[2], cbb[2],
                                              cmm[2], cmv[2], a3, 15, 45, 8, 23);
    dim3 g4(2, 2, 256);   // 23/16, 8/6
    conv_bn_pool<128,64><<<g4, 256, 55296>>>(a3, cw[3], ccb[3], cgm[3], cbb[3],
                                             cmm[3], cmv[3], a4, 8, 23, 4, 12);

    // ---- LSTM ----
    z0x_kernel<<<dim3(8, 48), 256>>>(lW0, lb0);
    cudaMemsetAsync(c0, 0, BATCH*NHID*sizeof(float));
    cudaMemsetAsync(c1, 0, BATCH*NHID*sizeof(float));

    for (int t = 0; t < TSTEPS; t++) {
        const float* h0_prev = (t == 0) ? zro : h0 + ((t+1)&1)*BATCH*NHID;
        float*       h0_out  = h0 + (t&1)*BATCH*NHID;
        // layer 0: gates = z0x[t] + h0_prev @ lW0[256:384,:]
        lstm_step<<<dim3(4,16), 128>>>(h0_prev, zro, NHID, 0,
                                       lW0 + 256*512,
                                       z0x + (size_t)t*BATCH*512, nullptr,
                                       c0, h0_out);
        // layer 1: gates = [h0_out | h1_prev] @ lW1 + lb1
        const float* h1_prev = (t == 0) ? zro : hs + (size_t)(t-1)*BATCH*NHID;
        lstm_step<<<dim3(4,16), 128>>>(h0_out, h1_prev, NHID, NHID,
                                       lW1, nullptr, lb1,
                                       c1, hs + (size_t)t*BATCH*NHID);
    }

    // ---- projection ----
    logits_kernel<<<444, 256>>>(Wout, bout, out);
}